// round 13
// baseline (speedup 1.0000x reference)
#include <cuda_runtime.h>
#include <math.h>

#define Bx 2
#define Lx 2048
#define Cx 1024
#define Hx 16
#define Dx 64
#define MTOT (Bx*Lx)          // 4096

__device__ float g_qkv[MTOT * 3 * Cx];                      // 50 MB
__device__ float g_attn[MTOT * Cx];                         // 16 MB

// ===========================================================================
// SGEMM 64x128 tile, k-chunks of 16, register-staged double buffer.
// 256 threads, 4x8 microtile, 3 blocks/SM (24 warps) for latency hiding.
// ===========================================================================
__device__ __forceinline__ void sgemm_core(const float* __restrict__ A,
                                           const float* __restrict__ Bw,
                                           const float* __restrict__ bias,
                                           float* __restrict__ Cc,
                                           int M, int N, int K)
{
    __shared__ float As[2][16][64];
    __shared__ float Bs[2][16][128];

    const int tid = threadIdx.x;
    const int m0 = blockIdx.y * 64;
    const int n0 = blockIdx.x * 128;
    const int tr = tid >> 4;          // 0..15 -> rows tr*4..+3
    const int tc = tid & 15;          // 0..15 -> cols tc*4 and 64+tc*4

    // A loader: 1 float4/thread/chunk. B loader: 2 float4/thread/chunk.
    const int arow = tid >> 2, akq = (tid & 3) * 4;
    const int f0 = tid * 2, f1 = tid * 2 + 1;
    const int brow0 = f0 >> 5, bcol0 = (f0 & 31) * 4;
    const int brow1 = f1 >> 5, bcol1 = (f1 & 31) * 4;

    float acc[4][8];
    #pragma unroll
    for (int i = 0; i < 4; ++i)
        #pragma unroll
        for (int j = 0; j < 8; ++j) acc[i][j] = 0.f;

    float4 ra, rb0, rb1;

    ra  = *reinterpret_cast<const float4*>(&A[(size_t)(m0 + arow) * K + akq]);
    rb0 = *reinterpret_cast<const float4*>(&Bw[(size_t)brow0 * N + n0 + bcol0]);
    rb1 = *reinterpret_cast<const float4*>(&Bw[(size_t)brow1 * N + n0 + bcol1]);
    As[0][akq + 0][arow] = ra.x; As[0][akq + 1][arow] = ra.y;
    As[0][akq + 2][arow] = ra.z; As[0][akq + 3][arow] = ra.w;
    *reinterpret_cast<float4*>(&Bs[0][brow0][bcol0]) = rb0;
    *reinterpret_cast<float4*>(&Bs[0][brow1][bcol1]) = rb1;
    __syncthreads();

    const int NC = K >> 4;
    for (int c = 0; c < NC; ++c) {
        const int buf = c & 1;
        if (c + 1 < NC) {
            const int kc = (c + 1) << 4;
            ra  = *reinterpret_cast<const float4*>(&A[(size_t)(m0 + arow) * K + kc + akq]);
            rb0 = *reinterpret_cast<const float4*>(&Bw[(size_t)(kc + brow0) * N + n0 + bcol0]);
            rb1 = *reinterpret_cast<const float4*>(&Bw[(size_t)(kc + brow1) * N + n0 + bcol1]);
        }

        #pragma unroll
        for (int k = 0; k < 16; ++k) {
            float4 av  = *reinterpret_cast<const float4*>(&As[buf][k][tr * 4]);
            float4 bv0 = *reinterpret_cast<const float4*>(&Bs[buf][k][tc * 4]);
            float4 bv1 = *reinterpret_cast<const float4*>(&Bs[buf][k][64 + tc * 4]);
            float a[4], b[8];
            a[0]=av.x; a[1]=av.y; a[2]=av.z; a[3]=av.w;
            b[0]=bv0.x; b[1]=bv0.y; b[2]=bv0.z; b[3]=bv0.w;
            b[4]=bv1.x; b[5]=bv1.y; b[6]=bv1.z; b[7]=bv1.w;
            #pragma unroll
            for (int i = 0; i < 4; ++i)
                #pragma unroll
                for (int j = 0; j < 8; ++j)
                    acc[i][j] += a[i] * b[j];
        }

        if (c + 1 < NC) {
            const int nb = (c + 1) & 1;
            As[nb][akq + 0][arow] = ra.x; As[nb][akq + 1][arow] = ra.y;
            As[nb][akq + 2][arow] = ra.z; As[nb][akq + 3][arow] = ra.w;
            *reinterpret_cast<float4*>(&Bs[nb][brow0][bcol0]) = rb0;
            *reinterpret_cast<float4*>(&Bs[nb][brow1][bcol1]) = rb1;
        }
        __syncthreads();
    }

    #pragma unroll
    for (int i = 0; i < 4; ++i) {
        const int m = m0 + tr * 4 + i;
        float4 lo, hi;
        lo.x = acc[i][0] + bias[n0 + tc * 4 + 0];
        lo.y = acc[i][1] + bias[n0 + tc * 4 + 1];
        lo.z = acc[i][2] + bias[n0 + tc * 4 + 2];
        lo.w = acc[i][3] + bias[n0 + tc * 4 + 3];
        hi.x = acc[i][4] + bias[n0 + 64 + tc * 4 + 0];
        hi.y = acc[i][5] + bias[n0 + 64 + tc * 4 + 1];
        hi.z = acc[i][6] + bias[n0 + 64 + tc * 4 + 2];
        hi.w = acc[i][7] + bias[n0 + 64 + tc * 4 + 3];
        *reinterpret_cast<float4*>(&Cc[(size_t)m * N + n0 + tc * 4]) = lo;
        *reinterpret_cast<float4*>(&Cc[(size_t)m * N + n0 + 64 + tc * 4]) = hi;
    }
}

__global__ void __launch_bounds__(256, 3)
qkv_gemm_kernel(const float* __restrict__ x, const float* __restrict__ W,
                const float* __restrict__ bias)
{
    sgemm_core(x, W, bias, g_qkv, MTOT, 3 * Cx, Cx);
}

__global__ void __launch_bounds__(256, 3)
out_gemm_kernel(const float* __restrict__ W, const float* __restrict__ bias,
                float* __restrict__ out)
{
    sgemm_core(g_attn, W, bias, out, MTOT, Cx, Cx);
}

// ---------------------------------------------------------------------------
// RMS norm + RoPE (in place on q,k). One warp per (token, head). [unchanged]
// ---------------------------------------------------------------------------
__global__ void norm_rope_kernel(const float* __restrict__ cosv,
                                 const float* __restrict__ sinv,
                                 const float* __restrict__ gq,
                                 const float* __restrict__ gk)
{
    const int warp = (blockIdx.x * blockDim.x + threadIdx.x) >> 5;
    const int lane = threadIdx.x & 31;
    const int m = warp >> 4;
    const int h = warp & 15;

    const float c = cosv[m * 32 + lane];
    const float s = sinv[m * 32 + lane];

    #pragma unroll
    for (int part = 0; part < 2; ++part) {
        float* ptr = &g_qkv[(size_t)m * 3072 + part * 1024 + h * 64];
        const float* gamma = (part == 0) ? gq : gk;
        float2 v = *reinterpret_cast<float2*>(ptr + 2 * lane);
        float ss = v.x * v.x + v.y * v.y;
        #pragma unroll
        for (int o = 16; o; o >>= 1) ss += __shfl_xor_sync(0xffffffffu, ss, o);
        const float inv = 8.0f / fmaxf(sqrtf(ss), 1e-12f);
        const float re = v.x * inv * gamma[h * 64 + 2 * lane];
        const float im = v.y * inv * gamma[h * 64 + 2 * lane + 1];
        float2 o2;
        o2.x = re * c - im * s;
        o2.y = re * s + im * c;
        *reinterpret_cast<float2*>(ptr + 2 * lane) = o2;
    }
}

// ===========================================================================
// Fused flash attention v3 [round-12, byte-identical]: fixed-shift softmax
// (scores provably <= 8), per-thread partial row sums, one final reduction.
// ===========================================================================
#define FL_QS (128 * 68)
#define FL_KS (64 * 70)
#define FL_VS (64 * 68)
#define FL_PS (128 * 68)
#define FL_SMEM_BYTES ((FL_QS + FL_KS + FL_VS + FL_PS) * 4)

__global__ void __launch_bounds__(256)
flash_attn_kernel()
{
    extern __shared__ float fsm[];
    float* Qs = fsm;
    float* Ks = fsm + FL_QS;
    float* Vs = Ks + FL_KS;
    float* Ps = Vs + FL_VS;

    const int bh = blockIdx.y;
    const int b = bh >> 4, h = bh & 15;
    const int l0 = blockIdx.x * 128;
    const int tid = threadIdx.x;
    const int tr = tid >> 4;
    const int tc = tid & 15;

    #pragma unroll
    for (int i = 0; i < 8; ++i) {
        const int e = tid + i * 256;
        const int row = e >> 4, c4 = (e & 15) * 4;
        float4 q = *reinterpret_cast<const float4*>(
            &g_qkv[(size_t)(b * Lx + l0 + row) * 3072 + h * 64 + c4]);
        q.x *= 0.125f; q.y *= 0.125f; q.z *= 0.125f; q.w *= 0.125f;
        *reinterpret_cast<float4*>(&Qs[row * 68 + c4]) = q;
    }

    float o[8][4];
    float lrow[8];
    #pragma unroll
    for (int i = 0; i < 8; ++i) {
        lrow[i] = 0.f;
        #pragma unroll
        for (int j = 0; j < 4; ++j) o[i][j] = 0.f;
    }

    for (int kb = 0; kb < Lx / 64; ++kb) {
        __syncthreads();
        #pragma unroll
        for (int i = 0; i < 4; ++i) {
            const int e = tid + i * 256;
            const int row = e >> 4, c4 = (e & 15) * 4;
            const float* base = &g_qkv[(size_t)(b * Lx + kb * 64 + row) * 3072 + h * 64 + c4];
            float4 kv = *reinterpret_cast<const float4*>(base + 1024);
            float2 k0; k0.x = kv.x; k0.y = kv.y;
            float2 k1; k1.x = kv.z; k1.y = kv.w;
            *reinterpret_cast<float2*>(&Ks[row * 70 + c4]) = k0;
            *reinterpret_cast<float2*>(&Ks[row * 70 + c4 + 2]) = k1;
            float4 vv = *reinterpret_cast<const float4*>(base + 2048);
            *reinterpret_cast<float4*>(&Vs[row * 68 + c4]) = vv;
        }
        __syncthreads();

        float s[8][4];
        #pragma unroll
        for (int i = 0; i < 8; ++i)
            #pragma unroll
            for (int j = 0; j < 4; ++j) s[i][j] = 0.f;

        #pragma unroll
        for (int d = 0; d < 64; d += 4) {
            float a[8][4];
            #pragma unroll
            for (int i = 0; i < 8; ++i) {
                float4 av = *reinterpret_cast<const float4*>(&Qs[(tr * 8 + i) * 68 + d]);
                a[i][0] = av.x; a[i][1] = av.y; a[i][2] = av.z; a[i][3] = av.w;
            }
            #pragma unroll
            for (int j = 0; j < 4; ++j) {
                float2 b0 = *reinterpret_cast<const float2*>(&Ks[(tc * 4 + j) * 70 + d]);
                float2 b1 = *reinterpret_cast<const float2*>(&Ks[(tc * 4 + j) * 70 + d + 2]);
                #pragma unroll
                for (int i = 0; i < 8; ++i)
                    s[i][j] += a[i][0] * b0.x + a[i][1] * b0.y
                             + a[i][2] * b1.x + a[i][3] * b1.y;
            }
        }

        #pragma unroll
        for (int i = 0; i < 8; ++i) {
            const float p0 = __expf(s[i][0] - 8.0f);
            const float p1 = __expf(s[i][1] - 8.0f);
            const float p2 = __expf(s[i][2] - 8.0f);
            const float p3 = __expf(s[i][3] - 8.0f);
            lrow[i] += (p0 + p1) + (p2 + p3);
            float4 pv; pv.x = p0; pv.y = p1; pv.z = p2; pv.w = p3;
            *reinterpret_cast<float4*>(&Ps[(tr * 8 + i) * 68 + tc * 4]) = pv;
        }
        __syncthreads();

        #pragma unroll
        for (int k = 0; k < 64; k += 4) {
            float a[8][4];
            #pragma unroll
            for (int i = 0; i < 8; ++i) {
                float4 av = *reinterpret_cast<const float4*>(&Ps[(tr * 8 + i) * 68 + k]);
                a[i][0] = av.x; a[i][1] = av.y; a[i][2] = av.z; a[i][3] = av.w;
            }
            #pragma unroll
            for (int kk = 0; kk < 4; ++kk) {
                float4 bv = *reinterpret_cast<const float4*>(&Vs[(k + kk) * 68 + tc * 4]);
                #pragma unroll
                for (int i = 0; i < 8; ++i) {
                    o[i][0] += a[i][kk] * bv.x;
                    o[i][1] += a[i][kk] * bv.y;
                    o[i][2] += a[i][kk] * bv.z;
                    o[i][3] += a[i][kk] * bv.w;
                }
            }
        }
    }

    #pragma unroll
    for (int i = 0; i < 8; ++i) {
        float l = lrow[i];
        l += __shfl_xor_sync(0xffffffffu, l, 8, 16);
        l += __shfl_xor_sync(0xffffffffu, l, 4, 16);
        l += __shfl_xor_sync(0xffffffffu, l, 2, 16);
        l += __shfl_xor_sync(0xffffffffu, l, 1, 16);
        const float inv = 1.0f / l;
        float4 ov;
        ov.x = o[i][0] * inv; ov.y = o[i][1] * inv;
        ov.z = o[i][2] * inv; ov.w = o[i][3] * inv;
        *reinterpret_cast<float4*>(
            &g_attn[(size_t)(b * Lx + l0 + tr * 8 + i) * 1024 + h * 64 + tc * 4]) = ov;
    }
}

// ---------------------------------------------------------------------------
extern "C" void kernel_launch(void* const* d_in, const int* in_sizes, int n_in,
                              void* d_out, int out_size)
{
    const float* x    = (const float*)d_in[0];
    const float* pcos = (const float*)d_in[1];
    const float* psin = (const float*)d_in[2];
    const float* Wqkv = (const float*)d_in[3];
    const float* bqkv = (const float*)d_in[4];
    const float* gq   = (const float*)d_in[5];
    const float* gk   = (const float*)d_in[6];
    const float* Wout = (const float*)d_in[7];
    const float* bout = (const float*)d_in[8];
    float* out = (float*)d_out;

    cudaFuncSetAttribute(flash_attn_kernel,
                         cudaFuncAttributeMaxDynamicSharedMemorySize, FL_SMEM_BYTES);

    // 1. QKV GEMM + bias -> g_qkv  (64-row tiles, 3 blocks/SM)
    qkv_gemm_kernel<<<dim3(3 * Cx / 128, MTOT / 64), 256>>>(x, Wqkv, bqkv);
    // 2. RMS norm + RoPE in place on q,k
    norm_rope_kernel<<<(MTOT * Hx) / 8, 256>>>(pcos, psin, gq, gk);
    // 3. Fused flash attention (fixed-shift softmax) -> g_attn
    flash_attn_kernel<<<dim3(Lx / 128, Bx * Hx), 256, FL_SMEM_BYTES>>>();
    // 4. Out GEMM + bias -> d_out
    out_gemm_kernel<<<dim3(Cx / 128, MTOT / 64), 256>>>(Wout, bout, out);
}